// round 14
// baseline (speedup 1.0000x reference)
#include <cuda_runtime.h>

#define TT 128
#define BB 512
#define QQ 50
#define BQ (BB * QQ)                 // 25600
#define NUNITS ((TT - 1) * BB)       // 65024
#define GAMMA_F 0.99f
#define UNITS 10                     // units per k_pairs block (10*25 = 250 thr)
#define RST 52                       // smem row stride, 16B aligned
#define GST 64                       // g_ret row stride (floats): 256B-aligned rows

// Discounted returns, row gu = t*BB+b at [gu*GST .. gu*GST+49], 256B-aligned.
__device__ __align__(256) float g_ret[NUNITS * GST];

// ---------------------------------------------------------------------------
// Kernel 1: backward recurrence. Block = (b, 64-t half); 1024 blocks.
// Lower half recomputes the upper composite locally (no cross-block dep).
// Stores are 56 floats/row (50 real + 6 pad) = 7 full 32B sectors -> no RMW.
// ---------------------------------------------------------------------------
__global__ __launch_bounds__(256)
void k_ret(const float* __restrict__ reward,
           const int*   __restrict__ step_type,
           const float* __restrict__ discount,
           const float* __restrict__ tvalue,
           float*       __restrict__ out)
{
    __shared__ __align__(16) float s_tv[TT][RST];   // rows t0..127 at [t-t0]
    __shared__ float s_a[TT], s_r[TT];
    __shared__ int   s_il[TT];
    __shared__ float s_A[8][RST], s_B[8][RST];

    const int tid = threadIdx.x;
    const int b   = blockIdx.x;
    const int h   = blockIdx.y;                      // 0: t 0..63, 1: t 64..126
    const int t0  = 64 * h;
    const int nrows = TT - t0;                       // staged rows (128 or 64)
    const int nsc   = TT - 1 - t0;                   // scalars for t0..126

    // Stage tvalue rows t0..127 (float2, coalesced)
    for (int idx = tid; idx < nrows * (QQ / 2); idx += 256) {
        const int lt = idx / (QQ / 2);
        const int q2 = idx - lt * (QQ / 2);
        ((float2*)&s_tv[lt][0])[q2] =
            *(const float2*)&tvalue[(t0 + lt) * BQ + b * QQ + 2 * q2];
    }
    // Per-t scalars, local index lt = t - t0
    if (tid < nsc) {
        const int t  = t0 + tid;
        const int il = step_type[t * BB + b];
        s_il[tid] = il;
        s_r[tid]  = reward[(t + 1) * BB + b];
        s_a[tid]  = (il == 2) ? 0.0f
                              : discount[(t + 1) * BB + b] * GAMMA_F;
    }
    if (h == 0 && tid == 0) out[(TT - 1) * BB + b] = 0.0f;   // poisoned row
    __syncthreads();

    const int nch = (nsc + 15) / 16;                 // h=0: 8 chunks, h=1: 4
    const int cg  = tid >> 6;                        // thread group 0..3
    const int q   = tid & 63;

    // ---- Phase A: group cg builds composites for chunks cg and cg+4 ----
    if (q < QQ) {
        #pragma unroll
        for (int rep = 0; rep < 2; ++rep) {
            const int cc = cg + 4 * rep;
            if (cc < nch) {
                const int llo = 16 * cc;
                const int lhi = min(llo + 15, nsc - 1);
                float A = 1.0f, Bv = 0.0f;
                for (int lt = lhi; lt >= llo; --lt) {
                    float a  = s_a[lt];
                    float bb = (s_il[lt] == 2) ? s_tv[lt][q] : s_r[lt];
                    A  = a * A;
                    Bv = fmaf(a, Bv, bb);
                }
                s_A[cc][q] = A;
                s_B[cc][q] = Bv;
            }
        }
    }
    __syncthreads();

    // ---- Phase B+C: group cg seeds chunk cg (compose higher chunks) and
    //      walks its 16 steps, writing padded g_ret rows ----
    if (q < QQ) {
        float carry = s_tv[TT - 1 - t0][q];          // rets[127] = tv[127]
        for (int cc = nch - 1; cc > cg; --cc)
            carry = fmaf(s_A[cc][q], carry, s_B[cc][q]);

        const int llo = 16 * cg;
        const int lhi = min(llo + 15, min(nsc, 64) - 1);  // walk only own half
        for (int lt = lhi; lt >= llo; --lt) {
            float a  = s_a[lt];
            float bb = (s_il[lt] == 2) ? s_tv[lt][q] : s_r[lt];
            carry = fmaf(a, carry, bb);
            g_ret[((t0 + lt) * BB + b) * GST + q] = carry;
        }
    } else if (q < 56) {
        // Pad columns 50..55 so each row's stores cover 7 full sectors.
        const int llo = 16 * cg;
        const int lhi = min(llo + 15, min(nsc, 64) - 1);
        for (int lt = lhi; lt >= llo; --lt)
            g_ret[((t0 + lt) * BB + b) * GST + q] = 0.0f;
    }
}

// ---------------------------------------------------------------------------
// Kernel 2: pairwise quantile-Huber (frozen R13 form, 37.8 us) — only the
// g_ret addressing changed to the 64-float row stride.
//   x = ret_i - v_j;  m = min(|x|,1);  c = (x&sign)|m;  t = x - 0.5c
//   h = c*t, sgn(x)*h = m*t ;  loss_j = 0.5*S + (tau_j-0.5)*D
// ---------------------------------------------------------------------------

#define PAIR2(r2_, nv2_, S2_, D2_) do {                                        \
    unsigned long long x2_, c2_, m2_, t2_;                                     \
    asm("add.rn.f32x2 %0, %1, %2;" : "=l"(x2_) : "l"(r2_), "l"(nv2_));         \
    float xl_, xh_;                                                            \
    asm("mov.b64 {%0, %1}, %2;" : "=f"(xl_), "=f"(xh_) : "l"(x2_));            \
    float ml_ = fminf(fabsf(xl_), 1.0f);                                       \
    float mh_ = fminf(fabsf(xh_), 1.0f);                                       \
    float cl_ = __int_as_float((__float_as_int(xl_) & 0x80000000) |            \
                               __float_as_int(ml_));                           \
    float ch_ = __int_as_float((__float_as_int(xh_) & 0x80000000) |            \
                               __float_as_int(mh_));                           \
    asm("mov.b64 %0, {%1, %2};" : "=l"(c2_) : "f"(cl_), "f"(ch_));             \
    asm("mov.b64 %0, {%1, %2};" : "=l"(m2_) : "f"(ml_), "f"(mh_));             \
    asm("fma.rn.f32x2 %0, %1, %2, %3;" : "=l"(t2_)                             \
        : "l"(c2_), "l"(MH2), "l"(x2_));                                       \
    asm("fma.rn.f32x2 %0, %1, %2, %0;" : "+l"(S2_) : "l"(c2_), "l"(t2_));      \
    asm("fma.rn.f32x2 %0, %1, %2, %0;" : "+l"(D2_) : "l"(m2_), "l"(t2_));      \
} while (0)

__global__ __launch_bounds__(256, 7)
void k_pairs(const float* __restrict__ value,
             float*       __restrict__ out)
{
    __shared__ __align__(16) float s_ret[UNITS][RST];
    __shared__ float s_part[UNITS][QQ];

    const int tid = threadIdx.x;
    const int gu0 = blockIdx.x * UNITS;
    const int nu  = min(UNITS, NUNITS - gu0);

    const int u  = tid / 25;
    const int jp = tid - u * 25;

    // Stage: per-unit 25 float2 loads from the 256B-aligned g_ret row.
    if (tid < UNITS * 25 && u < nu)
        ((float2*)&s_ret[u][0])[jp] =
            *(const float2*)&g_ret[(gu0 + u) * GST + 2 * jp];
    __syncthreads();

    if (tid < UNITS * 25 && u < nu) {
        const int gu = gu0 + u;
        const float2 v2 = *(const float2*)&value[gu * QQ + 2 * jp];
        unsigned long long nv2a, nv2b;
        {
            float na = -v2.x, nb = -v2.y;
            asm("mov.b64 %0, {%1, %1};" : "=l"(nv2a) : "f"(na));
            asm("mov.b64 %0, {%1, %1};" : "=l"(nv2b) : "f"(nb));
        }
        const unsigned long long MH2 = 0xBF000000BF000000ULL;   // (-0.5,-0.5)
        unsigned long long S2a = 0, D2a = 0, S2b = 0, D2b = 0;

        const ulonglong2* rp2 = (const ulonglong2*)&s_ret[u][0];
        #pragma unroll
        for (int p = 0; p < 12; ++p) {               // 48 returns via LDS.128
            ulonglong2 rr = rp2[p];
            PAIR2(rr.x, nv2a, S2a, D2a);
            PAIR2(rr.x, nv2b, S2b, D2b);
            PAIR2(rr.y, nv2a, S2a, D2a);
            PAIR2(rr.y, nv2b, S2b, D2b);
        }
        {                                            // returns 48, 49
            unsigned long long rt_ = *(const unsigned long long*)&s_ret[u][48];
            PAIR2(rt_, nv2a, S2a, D2a);
            PAIR2(rt_, nv2b, S2b, D2b);
        }

        float sl, sh, dl, dh;
        asm("mov.b64 {%0, %1}, %2;" : "=f"(sl), "=f"(sh) : "l"(S2a));
        asm("mov.b64 {%0, %1}, %2;" : "=f"(dl), "=f"(dh) : "l"(D2a));
        const float taua = (2 * jp + 0.5f) * (1.0f / QQ);
        s_part[u][2 * jp]     = fmaf(taua - 0.5f, dl + dh, 0.5f * (sl + sh));

        asm("mov.b64 {%0, %1}, %2;" : "=f"(sl), "=f"(sh) : "l"(S2b));
        asm("mov.b64 {%0, %1}, %2;" : "=f"(dl), "=f"(dh) : "l"(D2b));
        const float taub = (2 * jp + 1.5f) * (1.0f / QQ);
        s_part[u][2 * jp + 1] = fmaf(taub - 0.5f, dl + dh, 0.5f * (sl + sh));
    }
    __syncthreads();

    // Deterministic fixed-order j-reduction, one thread per unit.
    if (tid < nu) {
        float s = 0.0f;
        #pragma unroll
        for (int j = 0; j < QQ; ++j) s += s_part[tid][j];
        out[gu0 + tid] = s * (1.0f / QQ);            // out idx t*BB+b == gu
    }
}

extern "C" void kernel_launch(void* const* d_in, const int* in_sizes, int n_in,
                              void* d_out, int out_size)
{
    const float* reward    = (const float*)d_in[0];
    const int*   step_type = (const int*)  d_in[1];
    const float* discount  = (const float*)d_in[2];
    const float* value     = (const float*)d_in[3];
    const float* tvalue    = (const float*)d_in[4];
    float*       out       = (float*)d_out;

    dim3 gr(BB, 2);                                  // 1024 blocks
    k_ret<<<gr, 256>>>(reward, step_type, discount, tvalue, out);

    const int nblocks = (NUNITS + UNITS - 1) / UNITS;   // 6503
    k_pairs<<<nblocks, 256>>>(value, out);
}

// round 15
// speedup vs baseline: 1.0196x; 1.0196x over previous
#include <cuda_runtime.h>

#define TT 128
#define BB 512
#define QQ 50
#define BQ (BB * QQ)                 // 25600
#define NUNITS ((TT - 1) * BB)       // 65024
#define GAMMA_F 0.99f
#define UNITS 10
#define RST 52                       // smem row stride, 16B aligned
#define GST 64                       // g_ret row stride (floats), 256B-aligned
#define NPAIRB ((NUNITS + UNITS - 1) / UNITS)   // 6503
#define NBLK (BB + NPAIRB)                       // 7015

// Returns: row gu = t*BB+b at [gu*GST .. gu*GST+49].
__device__ __align__(256) float g_ret[NUNITS * GST];
// Per-b completion flags (zero-init; re-zeroed by memset node each replay).
__device__ int g_flag[BB];

__device__ __forceinline__ int ld_acquire(const int* p) {
    int v;
    asm volatile("ld.global.acquire.gpu.b32 %0, [%1];" : "=r"(v) : "l"(p));
    return v;
}
__device__ __forceinline__ void st_release(int* p, int v) {
    asm volatile("st.global.release.gpu.b32 [%0], %1;" :: "l"(p), "r"(v)
                 : "memory");
}

#define PAIR2(r2_, nv2_, S2_, D2_) do {                                        \
    unsigned long long x2_, c2_, m2_, t2_;                                     \
    asm("add.rn.f32x2 %0, %1, %2;" : "=l"(x2_) : "l"(r2_), "l"(nv2_));         \
    float xl_, xh_;                                                            \
    asm("mov.b64 {%0, %1}, %2;" : "=f"(xl_), "=f"(xh_) : "l"(x2_));            \
    float ml_ = fminf(fabsf(xl_), 1.0f);                                       \
    float mh_ = fminf(fabsf(xh_), 1.0f);                                       \
    float cl_ = __int_as_float((__float_as_int(xl_) & 0x80000000) |            \
                               __float_as_int(ml_));                           \
    float ch_ = __int_as_float((__float_as_int(xh_) & 0x80000000) |            \
                               __float_as_int(mh_));                           \
    asm("mov.b64 %0, {%1, %2};" : "=l"(c2_) : "f"(cl_), "f"(ch_));             \
    asm("mov.b64 %0, {%1, %2};" : "=l"(m2_) : "f"(ml_), "f"(mh_));             \
    asm("fma.rn.f32x2 %0, %1, %2, %3;" : "=l"(t2_)                             \
        : "l"(c2_), "l"(MH2), "l"(x2_));                                       \
    asm("fma.rn.f32x2 %0, %1, %2, %0;" : "+l"(S2_) : "l"(c2_), "l"(t2_));      \
    asm("fma.rn.f32x2 %0, %1, %2, %0;" : "+l"(D2_) : "l"(m2_), "l"(t2_));      \
} while (0)

// ---------------------------------------------------------------------------
// Combined kernel. bid < BB: recurrence producer for one b (R12's 4-way
// segmented scan). bid >= BB: pairwise consumer (frozen R14 k_pairs form),
// acquire-spinning on the <=10 per-b flags it depends on.
// ---------------------------------------------------------------------------
__global__ __launch_bounds__(256, 7)
void k_all(const float* __restrict__ reward,
           const int*   __restrict__ step_type,
           const float* __restrict__ discount,
           const float* __restrict__ value,
           const float* __restrict__ tvalue,
           float*       __restrict__ out)
{
    __shared__ __align__(16) float s_buf[TT * RST];   // 26.6KB, both roles
    __shared__ float s_sc[TT * 2];                    // ret: a | r
    __shared__ int   s_il[TT];
    __shared__ float s_AB[8 * RST];                   // ret: A[4] | B[4]

    const int tid = threadIdx.x;
    const int bid = blockIdx.x;

    if (bid < BB) {
        // ================= RET role =================
        const int b = bid;
        float (*s_tv)[RST] = (float(*)[RST])s_buf;
        float* s_a = s_sc;
        float* s_r = s_sc + TT;
        float (*s_A)[RST] = (float(*)[RST])s_AB;
        float (*s_B)[RST] = (float(*)[RST])(s_AB + 4 * RST);

        for (int idx = tid; idx < TT * (QQ / 2); idx += 256) {
            const int t  = idx / (QQ / 2);
            const int q2 = idx - t * (QQ / 2);
            ((float2*)&s_tv[t][0])[q2] =
                *(const float2*)&tvalue[t * BQ + b * QQ + 2 * q2];
        }
        if (tid < TT - 1) {
            const int il = step_type[tid * BB + b];
            s_il[tid] = il;
            s_r[tid]  = reward[(tid + 1) * BB + b];
            s_a[tid]  = (il == 2) ? 0.0f
                                  : discount[(tid + 1) * BB + b] * GAMMA_F;
        }
        if (tid == 0) out[(TT - 1) * BB + b] = 0.0f;   // poisoned last row
        __syncthreads();

        const int c  = tid >> 6;                       // chunk group 0..3
        const int q  = tid & 63;
        const int lo = 32 * c;
        const int hi = (c == 3) ? (TT - 2) : (lo + 31);

        if (q < QQ) {                                  // Phase A: composites
            float A = 1.0f, Bv = 0.0f;
            #pragma unroll 4
            for (int t = hi; t >= lo; --t) {
                float a  = s_a[t];
                float bb2 = (s_il[t] == 2) ? s_tv[t][q] : s_r[t];
                A  = a * A;
                Bv = fmaf(a, Bv, bb2);
            }
            s_A[c][q] = A;
            s_B[c][q] = Bv;
        }
        __syncthreads();

        if (q < QQ) {                                  // Phase B+C: seed+walk
            float carry = s_tv[TT - 1][q];             // rets[127]
            #pragma unroll
            for (int cc = 3; cc >= 1; --cc)
                if (cc > c) carry = fmaf(s_A[cc][q], carry, s_B[cc][q]);
            #pragma unroll 4
            for (int t = hi; t >= lo; --t) {
                float a  = s_a[t];
                float bb2 = (s_il[t] == 2) ? s_tv[t][q] : s_r[t];
                carry = fmaf(a, carry, bb2);
                g_ret[(t * BB + b) * GST + q] = carry;
            }
        }
        __syncthreads();
        if (tid == 0) st_release(&g_flag[b], 1);       // publish
    } else {
        // ================= PAIRS role =================
        const int pb  = bid - BB;
        const int gu0 = pb * UNITS;
        const int nu  = min(UNITS, NUNITS - gu0);
        float (*s_ret)[RST] = (float(*)[RST])s_buf;
        float (*s_part)[QQ] = (float(*)[QQ])(s_buf + 1024);

        // Wait for the <=10 producer b's this block depends on.
        if (tid < nu) {
            const int bb = (gu0 + tid) % BB;           // b of row gu0+tid
            while (ld_acquire(&g_flag[bb]) == 0) __nanosleep(200);
        }
        __syncthreads();

        const int u  = tid / 25;
        const int jp = tid - u * 25;

        if (tid < UNITS * 25 && u < nu)
            ((float2*)&s_ret[u][0])[jp] =
                *(const float2*)&g_ret[(gu0 + u) * GST + 2 * jp];
        __syncthreads();

        if (tid < UNITS * 25 && u < nu) {
            const int gu = gu0 + u;
            const float2 v2 = *(const float2*)&value[gu * QQ + 2 * jp];
            unsigned long long nv2a, nv2b;
            {
                float na = -v2.x, nb = -v2.y;
                asm("mov.b64 %0, {%1, %1};" : "=l"(nv2a) : "f"(na));
                asm("mov.b64 %0, {%1, %1};" : "=l"(nv2b) : "f"(nb));
            }
            const unsigned long long MH2 = 0xBF000000BF000000ULL; // (-0.5,-0.5)
            unsigned long long S2a = 0, D2a = 0, S2b = 0, D2b = 0;

            const ulonglong2* rp2 = (const ulonglong2*)&s_ret[u][0];
            #pragma unroll
            for (int p = 0; p < 12; ++p) {             // 48 returns, LDS.128
                ulonglong2 rr = rp2[p];
                PAIR2(rr.x, nv2a, S2a, D2a);
                PAIR2(rr.x, nv2b, S2b, D2b);
                PAIR2(rr.y, nv2a, S2a, D2a);
                PAIR2(rr.y, nv2b, S2b, D2b);
            }
            {                                          // returns 48, 49
                unsigned long long rt_ =
                    *(const unsigned long long*)&s_ret[u][48];
                PAIR2(rt_, nv2a, S2a, D2a);
                PAIR2(rt_, nv2b, S2b, D2b);
            }

            float sl, sh, dl, dh;
            asm("mov.b64 {%0, %1}, %2;" : "=f"(sl), "=f"(sh) : "l"(S2a));
            asm("mov.b64 {%0, %1}, %2;" : "=f"(dl), "=f"(dh) : "l"(D2a));
            const float taua = (2 * jp + 0.5f) * (1.0f / QQ);
            s_part[u][2 * jp]     = fmaf(taua - 0.5f, dl + dh, 0.5f * (sl + sh));

            asm("mov.b64 {%0, %1}, %2;" : "=f"(sl), "=f"(sh) : "l"(S2b));
            asm("mov.b64 {%0, %1}, %2;" : "=f"(dl), "=f"(dh) : "l"(D2b));
            const float taub = (2 * jp + 1.5f) * (1.0f / QQ);
            s_part[u][2 * jp + 1] = fmaf(taub - 0.5f, dl + dh, 0.5f * (sl + sh));
        }
        __syncthreads();

        // Deterministic fixed-order j-reduction, one thread per unit.
        if (tid < nu) {
            float s = 0.0f;
            #pragma unroll
            for (int j = 0; j < QQ; ++j) s += s_part[tid][j];
            out[gu0 + tid] = s * (1.0f / QQ);          // out idx t*BB+b == gu
        }
    }
}

extern "C" void kernel_launch(void* const* d_in, const int* in_sizes, int n_in,
                              void* d_out, int out_size)
{
    const float* reward    = (const float*)d_in[0];
    const int*   step_type = (const int*)  d_in[1];
    const float* discount  = (const float*)d_in[2];
    const float* value     = (const float*)d_in[3];
    const float* tvalue    = (const float*)d_in[4];
    float*       out       = (float*)d_out;

    // Reset producer flags (graph node; static zero-init covers first run too).
    void* flagp = nullptr;
    cudaGetSymbolAddress(&flagp, g_flag);
    cudaMemsetAsync(flagp, 0, BB * sizeof(int));

    k_all<<<NBLK, 256>>>(reward, step_type, discount, value, tvalue, out);
}